// round 12
// baseline (speedup 1.0000x reference)
#include <cuda_runtime.h>
#include <cuda_fp16.h>
#include <cstdint>

// ---------------------------------------------------------------------------
// Problem constants
// ---------------------------------------------------------------------------
constexpr int BROWS = 1024;    // batch (M)
constexpr int DIM   = 4096;    // in features (K)
constexpr int NCLS  = 50257;   // classes (N)
constexpr int LPAD  = 50260;   // padded scratch row stride (mult of 4)

constexpr int MT = 256;        // CTA tile M
constexpr int NT = 128;        // CTA tile N
constexpr int KT = 32;         // K fp16 per stage
constexpr int K_ITERS = DIM / KT;               // 128
constexpr int NTILES_N = (NCLS + NT - 1) / NT;  // 393
constexpr int THREADS = 512;   // 16 warps: 8m x 2n, warp tile 32x64

// SMEM stage: A_hi[256][32] A_lo[256][32] B[128][32], fp16, 64B rows swizzled
constexpr uint32_t AH_OFF = 0;
constexpr uint32_t AL_OFF = 16384;
constexpr uint32_t B_OFF  = 32768;
constexpr uint32_t STAGE_B = 40960;
constexpr int NSTAGE = 5;
constexpr uint32_t SMEM_TOTAL = NSTAGE * STAGE_B;   // 200 KB

// ---------------------------------------------------------------------------
// Device scratch (no allocations). 256B-aligned.
// ---------------------------------------------------------------------------
__device__ __align__(256) float  g_exp[(size_t)BROWS * LPAD];    // ~206 MB
__device__ __align__(256) float  g_rowsum[BROWS];
__device__ __align__(256) __half g_wh[(size_t)NCLS * DIM];       // 412 MB
__device__ __align__(256) __half g_xh[(size_t)BROWS * DIM];      // 8 MB
__device__ __align__(256) __half g_xl[(size_t)BROWS * DIM];      // 8 MB

// ---------------------------------------------------------------------------
// PTX helpers
// ---------------------------------------------------------------------------
__device__ __forceinline__ uint32_t smem_u32(const void* p) {
    uint32_t r;
    asm("{ .reg .u64 t; cvta.to.shared.u64 t, %1; cvt.u32.u64 %0, t; }"
        : "=r"(r) : "l"(p));
    return r;
}

__device__ __forceinline__ void cp16(uint32_t dst, const void* src) {
    asm volatile("cp.async.cg.shared.global [%0], [%1], 16;"
                 :: "r"(dst), "l"(src));
}
__device__ __forceinline__ void cp16z(uint32_t dst, const void* src, uint32_t sz) {
    asm volatile("cp.async.cg.shared.global [%0], [%1], 16, %2;"
                 :: "r"(dst), "l"(src), "r"(sz));
}
__device__ __forceinline__ void cp_commit() {
    asm volatile("cp.async.commit_group;" ::: "memory");
}
template <int N>
__device__ __forceinline__ void cp_wait() {
    asm volatile("cp.async.wait_group %0;" :: "n"(N) : "memory");
}

__device__ __forceinline__ void ldsm4(uint32_t* r, uint32_t addr) {
    asm volatile("ldmatrix.sync.aligned.m8n8.x4.shared.b16 {%0,%1,%2,%3}, [%4];"
                 : "=r"(r[0]), "=r"(r[1]), "=r"(r[2]), "=r"(r[3]) : "r"(addr));
}

__device__ __forceinline__ void mma_f16(float* c, const uint32_t* a, const uint32_t* b) {
    asm volatile(
        "mma.sync.aligned.m16n8k16.row.col.f32.f16.f16.f32 "
        "{%0,%1,%2,%3}, {%4,%5,%6,%7}, {%8,%9}, {%0,%1,%2,%3};"
        : "+f"(c[0]), "+f"(c[1]), "+f"(c[2]), "+f"(c[3])
        : "r"(a[0]), "r"(a[1]), "r"(a[2]), "r"(a[3]), "r"(b[0]), "r"(b[1]));
}

// Swizzled smem offset for [row][16B chunk], 64B rows; conflict-free ldmatrix
__device__ __forceinline__ uint32_t swz(uint32_t row, uint32_t ck) {
    return row * 64u + ((ck ^ ((row >> 1) & 3u)) << 4);
}

__device__ __forceinline__ uint32_t packh2(float a, float b) {
    __half2 v(__float2half_rn(a), __float2half_rn(b));
    return *reinterpret_cast<uint32_t*>(&v);
}

// ---------------------------------------------------------------------------
// Convert x: fp32 -> fp16 hi + fp16 lo (residual). Also zeroes g_rowsum.
// ---------------------------------------------------------------------------
__global__ void __launch_bounds__(256) conv_x(
    const float* __restrict__ in, __half* __restrict__ hi,
    __half* __restrict__ lo, int n4) {
    const int g0 = blockIdx.x * blockDim.x + threadIdx.x;
    if (g0 < BROWS) g_rowsum[g0] = 0.f;
    for (int i = g0; i < n4; i += gridDim.x * blockDim.x) {
        const float4 f = reinterpret_cast<const float4*>(in)[i];
        const float h0 = __half2float(__float2half_rn(f.x));
        const float h1 = __half2float(__float2half_rn(f.y));
        const float h2 = __half2float(__float2half_rn(f.z));
        const float h3 = __half2float(__float2half_rn(f.w));
        uint2 hv, lv;
        hv.x = packh2(f.x, f.y); hv.y = packh2(f.z, f.w);
        lv.x = packh2(f.x - h0, f.y - h1);
        lv.y = packh2(f.z - h2, f.w - h3);
        reinterpret_cast<uint2*>(hi)[i] = hv;
        reinterpret_cast<uint2*>(lo)[i] = lv;
    }
}

// ---------------------------------------------------------------------------
// Convert W: fp32 -> fp16
// ---------------------------------------------------------------------------
__global__ void __launch_bounds__(256) conv_w(
    const float* __restrict__ in, __half* __restrict__ outp, int n4) {
    for (int i = blockIdx.x * blockDim.x + threadIdx.x; i < n4;
         i += gridDim.x * blockDim.x) {
        const float4 f = reinterpret_cast<const float4*>(in)[i];
        uint2 v;
        v.x = packh2(f.x, f.y); v.y = packh2(f.z, f.w);
        reinterpret_cast<uint2*>(outp)[i] = v;
    }
}

// ---------------------------------------------------------------------------
// GEMM: e = exp(x @ W^T + b), 2-term fp16 split (x_hi + x_lo) @ W_h.
// CTA 256x128, 16 warps (8m x 2n), warp 32x64 -> 4 warps/SMSP.
// 5-stage cp.async pipeline, barrier every 2 iters, ALL loads post-barrier:
//   writes in window [B_e, B_e+2): slots (e+3)%5, (e+4)%5
//   reads  in window:              slots  e%5,    (e+1)%5   -> disjoint.
//   cp_wait<1> + barrier publishes groups <= e+1 (stages e, e+1) to all warps.
// ---------------------------------------------------------------------------
__global__ void __launch_bounds__(THREADS, 1) svp_gemm(const float* __restrict__ bias) {
    extern __shared__ char smem[];
    const uint32_t sb = smem_u32(smem);
    const int tid  = threadIdx.x;
    const int wid  = tid >> 5;
    const int lane = tid & 31;
    const int wm = wid >> 1;          // 0..7 (32 rows each)
    const int wn = wid & 1;           // 0..1 (64 cols each)

    const int m0 = blockIdx.x * MT;
    const int n0 = blockIdx.y * NT;

    auto load_stage = [&](int kc) {
        const uint32_t st = sb + (uint32_t)(kc % NSTAGE) * STAGE_B;
        const int kb = kc * KT;
        // A: 256 rows x 4 chunks of 16B, hi+lo (1024 pairs / 512 thr = 2 each)
        #pragma unroll
        for (int i = 0; i < 2; ++i) {
            const int id  = tid + i * THREADS;   // 0..1023
            const int row = id >> 2;
            const int ck  = id & 3;
            const uint32_t d = st + swz((uint32_t)row, (uint32_t)ck);
            const size_t gi = (size_t)(m0 + row) * DIM + kb + ck * 8;
            cp16(d + AH_OFF, g_xh + gi);
            cp16(d + AL_OFF, g_xl + gi);
        }
        // B: 128 rows x 4 chunks (512 = 1 per thread), zero past NCLS
        {
            const int row = tid >> 2;
            const int ck  = tid & 3;
            const int n   = n0 + row;
            const uint32_t sz = (n < NCLS) ? 16u : 0u;
            const int nn = (n < NCLS) ? n : 0;
            const uint32_t d = st + B_OFF + swz((uint32_t)row, (uint32_t)ck);
            cp16z(d, g_wh + (size_t)nn * DIM + kb + ck * 8, sz);
        }
    };

    float acc[2][8][4];
    #pragma unroll
    for (int a = 0; a < 2; ++a)
        #pragma unroll
        for (int b = 0; b < 8; ++b)
            #pragma unroll
            for (int c = 0; c < 4; ++c) acc[a][b][c] = 0.f;

    auto compute_iter = [&](int it) {
        const uint32_t stA = sb + (uint32_t)(it % NSTAGE) * STAGE_B;
        const uint32_t stB = stA + B_OFF;
        #pragma unroll
        for (int kk = 0; kk < 2; ++kk) {
            uint32_t ah[2][4], al[2][4];
            {
                const uint32_t r = (uint32_t)(wm * 32 + (lane & 15));
                const uint32_t c = (uint32_t)(kk * 2 + (lane >> 4));
                #pragma unroll
                for (int mt = 0; mt < 2; ++mt) {
                    const uint32_t ad = stA + swz(r + mt * 16u, c);
                    ldsm4(ah[mt], ad + AH_OFF);
                    ldsm4(al[mt], ad + AL_OFF);
                }
            }
            #pragma unroll
            for (int h = 0; h < 2; ++h) {
                uint32_t bb[2][4];
                {
                    const uint32_t rb =
                        (uint32_t)(wn * 64 + h * 32 + (lane & 7) + ((lane & 16) >> 1));
                    const uint32_t c = (uint32_t)(kk * 2 + ((lane >> 3) & 1));
                    #pragma unroll
                    for (int q = 0; q < 2; ++q)
                        ldsm4(bb[q], stB + swz(rb + q * 16u, c));
                }
                #pragma unroll
                for (int mt = 0; mt < 2; ++mt)
                    #pragma unroll
                    for (int q = 0; q < 2; ++q)
                        #pragma unroll
                        for (int t = 0; t < 2; ++t)
                            mma_f16(acc[mt][h * 4 + q * 2 + t], ah[mt], &bb[q][t * 2]);
                #pragma unroll
                for (int mt = 0; mt < 2; ++mt)
                    #pragma unroll
                    for (int q = 0; q < 2; ++q)
                        #pragma unroll
                        for (int t = 0; t < 2; ++t)
                            mma_f16(acc[mt][h * 4 + q * 2 + t], al[mt], &bb[q][t * 2]);
            }
        }
    };

    // prologue: stages 0,1,2 in flight (groups 0,1,2)
    load_stage(0); cp_commit();
    load_stage(1); cp_commit();
    load_stage(2); cp_commit();

    #pragma unroll 1
    for (int e = 0; e < K_ITERS; e += 2) {
        // publish stages e, e+1 to every warp (own groups <= e+1 complete + bar)
        cp_wait<1>();
        __syncthreads();

        if (e + 3 < K_ITERS) load_stage(e + 3);
        cp_commit();

        compute_iter(e);

        if (e + 4 < K_ITERS) load_stage(e + 4);
        cp_commit();

        compute_iter(e + 1);
    }

    // ---- epilogue: e = exp(acc + bias); store; row-sum via atomics ----
    #pragma unroll
    for (int mt = 0; mt < 2; ++mt) {
        const int r0 = m0 + wm * 32 + mt * 16 + (lane >> 2);
        float rs0 = 0.f, rs1 = 0.f;
        #pragma unroll
        for (int nt = 0; nt < 8; ++nt) {
            const int n = n0 + wn * 64 + nt * 8 + (lane & 3) * 2;
            if (n >= NCLS) continue;
            const float b0 = __ldg(bias + n);
            const bool ok1 = (n + 1) < NCLS;
            const float* cc = acc[mt][nt];
            const float e00 = __expf(cc[0] + b0);
            const float e10 = __expf(cc[2] + b0);
            float* o0 = g_exp + (size_t)r0 * LPAD + n;
            float* o1 = g_exp + (size_t)(r0 + 8) * LPAD + n;
            if (ok1) {
                const float b1v = __ldg(bias + n + 1);
                const float e01 = __expf(cc[1] + b1v);
                const float e11 = __expf(cc[3] + b1v);
                *reinterpret_cast<float2*>(o0) = make_float2(e00, e01);
                *reinterpret_cast<float2*>(o1) = make_float2(e10, e11);
                rs0 += e00 + e01;
                rs1 += e10 + e11;
            } else {
                o0[0] = e00; o1[0] = e10;
                rs0 += e00;  rs1 += e10;
            }
        }
        rs0 += __shfl_xor_sync(0xFFFFFFFF, rs0, 1);
        rs0 += __shfl_xor_sync(0xFFFFFFFF, rs0, 2);
        rs1 += __shfl_xor_sync(0xFFFFFFFF, rs1, 1);
        rs1 += __shfl_xor_sync(0xFFFFFFFF, rs1, 2);
        if ((lane & 3) == 0) {
            atomicAdd(g_rowsum + r0, rs0);
            atomicAdd(g_rowsum + r0 + 8, rs1);
        }
    }
}

// ---------------------------------------------------------------------------
// Normalize: out = e * (1 / rowsum). One CTA per row.
// ---------------------------------------------------------------------------
__global__ void __launch_bounds__(256) svp_norm(float* __restrict__ out) {
    const int tid = threadIdx.x;
    const int row = blockIdx.x;
    const float* e = g_exp + (size_t)row * LPAD;
    float* o = out + (size_t)row * NCLS;
    const float inv = 1.f / g_rowsum[row];
    for (int i = tid; i < NCLS; i += 256) o[i] = e[i] * inv;
}

// Dummy kernel: keeps svp_gemm at profiled launch index 5.
__global__ void svp_dummy() {}

// ---------------------------------------------------------------------------
// Launch
// ---------------------------------------------------------------------------
extern "C" void kernel_launch(void* const* d_in, const int* in_sizes, int n_in,
                              void* d_out, int out_size) {
    const float* x = (const float*)d_in[0];   // [1024, 4096]
    const float* W = (const float*)d_in[1];   // [50257, 4096]
    const float* b = (const float*)d_in[2];   // [50257]
    float* out = (float*)d_out;               // [1024, 50257]

    __half *wh, *xh, *xl;
    cudaGetSymbolAddress((void**)&wh, g_wh);
    cudaGetSymbolAddress((void**)&xh, g_xh);
    cudaGetSymbolAddress((void**)&xl, g_xl);

    conv_x<<<1024, 256>>>(x, xh, xl, BROWS * DIM / 4);   // also zeroes rowsum
    conv_w<<<8192, 256>>>(W, wh, NCLS * DIM / 4);

    svp_dummy<<<1, 32>>>();

    cudaFuncSetAttribute(svp_gemm, cudaFuncAttributeMaxDynamicSharedMemorySize,
                         SMEM_TOTAL);
    dim3 grid(BROWS / MT, NTILES_N);   // (4, 393), m fastest for W reuse in L2
    svp_gemm<<<grid, THREADS, SMEM_TOTAL>>>(b);

    svp_norm<<<BROWS, 256>>>(out);
}

// round 13
// speedup vs baseline: 1.0133x; 1.0133x over previous
#include <cuda_runtime.h>
#include <cuda_fp16.h>
#include <cstdint>

// ---------------------------------------------------------------------------
// Problem constants
// ---------------------------------------------------------------------------
constexpr int BROWS = 1024;    // batch (M)
constexpr int DIM   = 4096;    // in features (K)
constexpr int NCLS  = 50257;   // classes (N)
constexpr int LPAD  = 50260;   // padded scratch row stride (mult of 4)

constexpr int MT = 256;        // CTA tile M
constexpr int NT = 128;        // CTA tile N
constexpr int KT = 32;         // K fp16 per stage
constexpr int K_ITERS = DIM / KT;               // 128
constexpr int NTILES_N = (NCLS + NT - 1) / NT;  // 393
constexpr int THREADS = 512;   // 16 warps: 8m x 2n, warp tile 32x64

constexpr int MTILES = BROWS / 16;   // 64
constexpr int KTILES = DIM / 16;     // 256

// SMEM stage: B[128][32] fp16, 64B rows swizzled (A lives in registers now)
constexpr uint32_t STAGE_B = 8192;
constexpr int NSTAGE = 5;
constexpr uint32_t SMEM_TOTAL = NSTAGE * STAGE_B;   // 40 KB

// ---------------------------------------------------------------------------
// Device scratch (no allocations). 256B-aligned.
// ---------------------------------------------------------------------------
__device__ __align__(256) float    g_exp[(size_t)BROWS * LPAD];    // ~206 MB
__device__ __align__(256) float    g_rowsum[BROWS];
__device__ __align__(256) __half   g_wh[(size_t)NCLS * DIM];       // 412 MB
// x in fragment-major layout: frag (mtile,ktile) = 1KB: hi[32 lanes x 16B] | lo
__device__ __align__(256) uint32_t g_xf[(size_t)MTILES * KTILES * 256];  // 16 MB

// ---------------------------------------------------------------------------
// PTX helpers
// ---------------------------------------------------------------------------
__device__ __forceinline__ uint32_t smem_u32(const void* p) {
    uint32_t r;
    asm("{ .reg .u64 t; cvta.to.shared.u64 t, %1; cvt.u32.u64 %0, t; }"
        : "=r"(r) : "l"(p));
    return r;
}

__device__ __forceinline__ void cp16z(uint32_t dst, const void* src, uint32_t sz) {
    asm volatile("cp.async.cg.shared.global [%0], [%1], 16, %2;"
                 :: "r"(dst), "l"(src), "r"(sz));
}
__device__ __forceinline__ void cp_commit() {
    asm volatile("cp.async.commit_group;" ::: "memory");
}
template <int N>
__device__ __forceinline__ void cp_wait() {
    asm volatile("cp.async.wait_group %0;" :: "n"(N) : "memory");
}

__device__ __forceinline__ void ldsm4(uint32_t* r, uint32_t addr) {
    asm volatile("ldmatrix.sync.aligned.m8n8.x4.shared.b16 {%0,%1,%2,%3}, [%4];"
                 : "=r"(r[0]), "=r"(r[1]), "=r"(r[2]), "=r"(r[3]) : "r"(addr));
}

__device__ __forceinline__ void mma_f16(float* c, const uint32_t* a, const uint32_t* b) {
    asm volatile(
        "mma.sync.aligned.m16n8k16.row.col.f32.f16.f16.f32 "
        "{%0,%1,%2,%3}, {%4,%5,%6,%7}, {%8,%9}, {%0,%1,%2,%3};"
        : "+f"(c[0]), "+f"(c[1]), "+f"(c[2]), "+f"(c[3])
        : "r"(a[0]), "r"(a[1]), "r"(a[2]), "r"(a[3]), "r"(b[0]), "r"(b[1]));
}

// Swizzled smem offset for [row][16B chunk], 64B rows; conflict-free ldmatrix
__device__ __forceinline__ uint32_t swz(uint32_t row, uint32_t ck) {
    return row * 64u + ((ck ^ ((row >> 1) & 3u)) << 4);
}

__device__ __forceinline__ uint32_t packh2(float a, float b) {
    __half2 v(__float2half_rn(a), __float2half_rn(b));
    return *reinterpret_cast<uint32_t*>(&v);
}

// ---------------------------------------------------------------------------
// conv_x_frag: x fp32 -> fragment-major fp16 hi/lo.
// One warp per (mtile, ktile) fragment. Lane l holds mma-A regs:
//   a0=(r, c..c+1)  a1=(r+8, c..c+1)  a2=(r, c+8..c+9)  a3=(r+8, c+8..c+9)
//   with r = l>>2, c = 2*(l&3).   Stored: hi uint4 @ lane*16B, lo @ +512B.
// ---------------------------------------------------------------------------
__global__ void __launch_bounds__(256) conv_x_frag(
    const float* __restrict__ x, uint32_t* __restrict__ xf) {
    const int gid = blockIdx.x * 256 + threadIdx.x;
    if (gid < BROWS) g_rowsum[gid] = 0.f;
    const int w = gid >> 5;                 // fragment id
    if (w >= MTILES * KTILES) return;
    const int lane  = threadIdx.x & 31;
    const int mtile = w >> 8;               // w / KTILES
    const int ktile = w & 255;
    const int r = lane >> 2;
    const int c = (lane & 3) * 2;

    const float* base = x + (size_t)(mtile * 16 + r) * DIM + ktile * 16 + c;
    const float2 v0 = *reinterpret_cast<const float2*>(base);
    const float2 v1 = *reinterpret_cast<const float2*>(base + 8 * DIM);
    const float2 v2 = *reinterpret_cast<const float2*>(base + 8);
    const float2 v3 = *reinterpret_cast<const float2*>(base + 8 * DIM + 8);

    uint4 hi, lo;
    {
        const float h00 = __half2float(__float2half_rn(v0.x));
        const float h01 = __half2float(__float2half_rn(v0.y));
        const float h10 = __half2float(__float2half_rn(v1.x));
        const float h11 = __half2float(__float2half_rn(v1.y));
        const float h20 = __half2float(__float2half_rn(v2.x));
        const float h21 = __half2float(__float2half_rn(v2.y));
        const float h30 = __half2float(__float2half_rn(v3.x));
        const float h31 = __half2float(__float2half_rn(v3.y));
        hi.x = packh2(v0.x, v0.y); hi.y = packh2(v1.x, v1.y);
        hi.z = packh2(v2.x, v2.y); hi.w = packh2(v3.x, v3.y);
        lo.x = packh2(v0.x - h00, v0.y - h01);
        lo.y = packh2(v1.x - h10, v1.y - h11);
        lo.z = packh2(v2.x - h20, v2.y - h21);
        lo.w = packh2(v3.x - h30, v3.y - h31);
    }
    uint4* dst = reinterpret_cast<uint4*>(xf) + (size_t)w * 64 + lane;
    dst[0]  = hi;
    dst[32] = lo;
}

// ---------------------------------------------------------------------------
// Convert W: fp32 -> fp16
// ---------------------------------------------------------------------------
__global__ void __launch_bounds__(256) conv_w(
    const float* __restrict__ in, __half* __restrict__ outp, int n4) {
    for (int i = blockIdx.x * blockDim.x + threadIdx.x; i < n4;
         i += gridDim.x * blockDim.x) {
        const float4 f = reinterpret_cast<const float4*>(in)[i];
        uint2 v;
        v.x = packh2(f.x, f.y); v.y = packh2(f.z, f.w);
        reinterpret_cast<uint2*>(outp)[i] = v;
    }
}

// ---------------------------------------------------------------------------
// GEMM: e = exp(x @ W^T + b), 2-term fp16 split (x_hi + x_lo) @ W_h.
// CTA 256x128, 16 warps (8m x 2n), warp 32x64.
// A: fragment-major LDG.128 from gmem (L2-resident), register double-buffered
//    one kk ahead. B: smem, 5-stage cp.async, barrier every 2 iters
//    (writes -> slots (e+3)%5,(e+4)%5; reads -> e%5,(e+1)%5; disjoint).
// Smem traffic/iter: 64KB ldsm read + 8KB cp write = ~72 B/cyc << 128 cap.
// ---------------------------------------------------------------------------
__global__ void __launch_bounds__(THREADS, 1) svp_gemm(const float* __restrict__ bias) {
    extern __shared__ char smem[];
    const uint32_t sb = smem_u32(smem);
    const int tid  = threadIdx.x;
    const int wid  = tid >> 5;
    const int lane = tid & 31;
    const int wm = wid >> 1;          // 0..7 (32 rows each)
    const int wn = wid & 1;           // 0..1 (64 cols each)

    const int m0 = blockIdx.x * MT;
    const int n0 = blockIdx.y * NT;
    const int mtile_base = (m0 >> 4) + wm * 2;

    const uint4* xf4 = reinterpret_cast<const uint4*>(g_xf);

    // B-only stage loader: 128 rows x 4 chunks of 16B = 512 cp (1/thread)
    auto load_stage = [&](int kc) {
        const uint32_t st = sb + (uint32_t)(kc % NSTAGE) * STAGE_B;
        const int kb = kc * KT;
        const int row = tid >> 2;
        const int ck  = tid & 3;
        const int n   = n0 + row;
        const uint32_t sz = (n < NCLS) ? 16u : 0u;
        const int nn = (n < NCLS) ? n : 0;
        const uint32_t d = st + swz((uint32_t)row, (uint32_t)ck);
        cp16z(d, g_wh + (size_t)nn * DIM + kb + ck * 8, sz);
    };

    // A fragment register buffers: [kk parity][mt][hi0..3, lo0..3]
    uint32_t af[2][2][8];
    auto load_af = [&](int buf, int it, int kk) {
        const int kt = it * 2 + kk;
        #pragma unroll
        for (int mt = 0; mt < 2; ++mt) {
            const uint4* p = xf4 +
                ((size_t)(mtile_base + mt) * KTILES + kt) * 64 + lane;
            const uint4 h = __ldg(p);
            const uint4 l = __ldg(p + 32);
            af[buf][mt][0] = h.x; af[buf][mt][1] = h.y;
            af[buf][mt][2] = h.z; af[buf][mt][3] = h.w;
            af[buf][mt][4] = l.x; af[buf][mt][5] = l.y;
            af[buf][mt][6] = l.z; af[buf][mt][7] = l.w;
        }
    };

    float acc[2][8][4];
    #pragma unroll
    for (int a = 0; a < 2; ++a)
        #pragma unroll
        for (int b = 0; b < 8; ++b)
            #pragma unroll
            for (int c = 0; c < 4; ++c) acc[a][b][c] = 0.f;

    auto compute_iter = [&](int it) {
        const uint32_t stB = sb + (uint32_t)(it % NSTAGE) * STAGE_B;
        #pragma unroll
        for (int kk = 0; kk < 2; ++kk) {
            // prefetch the next kk's A fragments (distance ~1 kk of MMAs)
            if (kk == 0) load_af(1, it, 1);
            else if (it + 1 < K_ITERS) load_af(0, it + 1, 0);

            #pragma unroll
            for (int h = 0; h < 2; ++h) {
                uint32_t bb[2][4];
                {
                    const uint32_t rb =
                        (uint32_t)(wn * 64 + h * 32 + (lane & 7) + ((lane & 16) >> 1));
                    const uint32_t c = (uint32_t)(kk * 2 + ((lane >> 3) & 1));
                    #pragma unroll
                    for (int q = 0; q < 2; ++q)
                        ldsm4(bb[q], stB + swz(rb + q * 16u, c));
                }
                #pragma unroll
                for (int mt = 0; mt < 2; ++mt)
                    #pragma unroll
                    for (int q = 0; q < 2; ++q)
                        #pragma unroll
                        for (int t = 0; t < 2; ++t)
                            mma_f16(acc[mt][h * 4 + q * 2 + t],
                                    &af[kk][mt][0], &bb[q][t * 2]);
                #pragma unroll
                for (int mt = 0; mt < 2; ++mt)
                    #pragma unroll
                    for (int q = 0; q < 2; ++q)
                        #pragma unroll
                        for (int t = 0; t < 2; ++t)
                            mma_f16(acc[mt][h * 4 + q * 2 + t],
                                    &af[kk][mt][4], &bb[q][t * 2]);
            }
        }
    };

    // prologue: B stages 0,1,2 in flight; A frags for (0,0)
    load_stage(0); cp_commit();
    load_stage(1); cp_commit();
    load_stage(2); cp_commit();
    load_af(0, 0, 0);

    #pragma unroll 1
    for (int e = 0; e < K_ITERS; e += 2) {
        // publish stages e, e+1 to every warp
        cp_wait<1>();
        __syncthreads();

        if (e + 3 < K_ITERS) load_stage(e + 3);
        cp_commit();

        compute_iter(e);

        if (e + 4 < K_ITERS) load_stage(e + 4);
        cp_commit();

        compute_iter(e + 1);
    }

    // ---- epilogue: e = exp(acc + bias); store; row-sum via atomics ----
    #pragma unroll
    for (int mt = 0; mt < 2; ++mt) {
        const int r0 = m0 + wm * 32 + mt * 16 + (lane >> 2);
        float rs0 = 0.f, rs1 = 0.f;
        #pragma unroll
        for (int nt = 0; nt < 8; ++nt) {
            const int n = n0 + wn * 64 + nt * 8 + (lane & 3) * 2;
            if (n >= NCLS) continue;
            const float b0 = __ldg(bias + n);
            const bool ok1 = (n + 1) < NCLS;
            const float* cc = acc[mt][nt];
            const float e00 = __expf(cc[0] + b0);
            const float e10 = __expf(cc[2] + b0);
            float* o0 = g_exp + (size_t)r0 * LPAD + n;
            float* o1 = g_exp + (size_t)(r0 + 8) * LPAD + n;
            if (ok1) {
                const float b1v = __ldg(bias + n + 1);
                const float e01 = __expf(cc[1] + b1v);
                const float e11 = __expf(cc[3] + b1v);
                *reinterpret_cast<float2*>(o0) = make_float2(e00, e01);
                *reinterpret_cast<float2*>(o1) = make_float2(e10, e11);
                rs0 += e00 + e01;
                rs1 += e10 + e11;
            } else {
                o0[0] = e00; o1[0] = e10;
                rs0 += e00;  rs1 += e10;
            }
        }
        rs0 += __shfl_xor_sync(0xFFFFFFFF, rs0, 1);
        rs0 += __shfl_xor_sync(0xFFFFFFFF, rs0, 2);
        rs1 += __shfl_xor_sync(0xFFFFFFFF, rs1, 1);
        rs1 += __shfl_xor_sync(0xFFFFFFFF, rs1, 2);
        if ((lane & 3) == 0) {
            atomicAdd(g_rowsum + r0, rs0);
            atomicAdd(g_rowsum + r0 + 8, rs1);
        }
    }
}

// ---------------------------------------------------------------------------
// Normalize: out = e * (1 / rowsum). One CTA per row.
// ---------------------------------------------------------------------------
__global__ void __launch_bounds__(256) svp_norm(float* __restrict__ out) {
    const int tid = threadIdx.x;
    const int row = blockIdx.x;
    const float* e = g_exp + (size_t)row * LPAD;
    float* o = out + (size_t)row * NCLS;
    const float inv = 1.f / g_rowsum[row];
    for (int i = tid; i < NCLS; i += 256) o[i] = e[i] * inv;
}

// Dummy kernel: keeps svp_gemm at profiled launch index 5.
__global__ void svp_dummy() {}

// ---------------------------------------------------------------------------
// Launch
// ---------------------------------------------------------------------------
extern "C" void kernel_launch(void* const* d_in, const int* in_sizes, int n_in,
                              void* d_out, int out_size) {
    const float* x = (const float*)d_in[0];   // [1024, 4096]
    const float* W = (const float*)d_in[1];   // [50257, 4096]
    const float* b = (const float*)d_in[2];   // [50257]
    float* out = (float*)d_out;               // [1024, 50257]

    __half* wh;
    uint32_t* xf;
    cudaGetSymbolAddress((void**)&wh, g_wh);
    cudaGetSymbolAddress((void**)&xf, g_xf);

    // 16384 fragments, 8 warps per block -> 2048 blocks (also zeroes rowsum)
    conv_x_frag<<<2048, 256>>>(x, xf);
    conv_w<<<8192, 256>>>(W, wh, NCLS * DIM / 4);

    svp_dummy<<<1, 32>>>();

    cudaFuncSetAttribute(svp_gemm, cudaFuncAttributeMaxDynamicSharedMemorySize,
                         SMEM_TOTAL);
    dim3 grid(BROWS / MT, NTILES_N);   // (4, 393), m fastest for W reuse in L2
    svp_gemm<<<grid, THREADS, SMEM_TOTAL>>>(b);

    svp_norm<<<BROWS, 256>>>(out);
}

// round 15
// speedup vs baseline: 1.5564x; 1.5359x over previous
#include <cuda_runtime.h>
#include <cuda_fp16.h>
#include <cstdint>

// ---------------------------------------------------------------------------
// Problem constants
// ---------------------------------------------------------------------------
constexpr int BROWS = 1024;    // batch (M)
constexpr int DIM   = 4096;    // in features (K)
constexpr int NCLS  = 50257;   // classes (N)
constexpr int LPAD  = 50260;   // padded scratch row stride (mult of 4)

constexpr int MT = 256;        // CTA tile M
constexpr int NT = 128;        // CTA tile N
constexpr int KT = 32;         // K fp16 per stage
constexpr int K_ITERS = DIM / KT;               // 128
constexpr int NTILES_N = (NCLS + NT - 1) / NT;  // 393
constexpr int THREADS = 512;   // 16 warps: 8m x 2n, warp tile 32x64

constexpr int MTILES = BROWS / 16;   // 64
constexpr int KTILES = DIM / 16;     // 256

// SMEM stage: B[128][32] fp16, 64B rows swizzled (A lives in registers)
constexpr uint32_t STAGE_B = 8192;
constexpr int NSTAGE = 5;
constexpr uint32_t SMEM_TOTAL = NSTAGE * STAGE_B;   // 40 KB

// ---------------------------------------------------------------------------
// Device scratch (no allocations). 256B-aligned.
// ---------------------------------------------------------------------------
__device__ __align__(256) float    g_exp[(size_t)BROWS * LPAD];    // ~206 MB
__device__ __align__(256) float    g_rowsum[BROWS];
__device__ __align__(256) __half   g_wh[(size_t)NCLS * DIM];       // 412 MB
// x fragment-major fp16: frag (mtile,ktile) = 512B = 32 lanes x 16B (mma A regs)
__device__ __align__(256) uint32_t g_xf[(size_t)MTILES * KTILES * 128];  // 8 MB

// ---------------------------------------------------------------------------
// PTX helpers
// ---------------------------------------------------------------------------
__device__ __forceinline__ uint32_t smem_u32(const void* p) {
    uint32_t r;
    asm("{ .reg .u64 t; cvta.to.shared.u64 t, %1; cvt.u32.u64 %0, t; }"
        : "=r"(r) : "l"(p));
    return r;
}

__device__ __forceinline__ void cp16z(uint32_t dst, const void* src, uint32_t sz) {
    asm volatile("cp.async.cg.shared.global [%0], [%1], 16, %2;"
                 :: "r"(dst), "l"(src), "r"(sz));
}
__device__ __forceinline__ void cp_commit() {
    asm volatile("cp.async.commit_group;" ::: "memory");
}
template <int N>
__device__ __forceinline__ void cp_wait() {
    asm volatile("cp.async.wait_group %0;" :: "n"(N) : "memory");
}

__device__ __forceinline__ void ldsm4(uint32_t* r, uint32_t addr) {
    asm volatile("ldmatrix.sync.aligned.m8n8.x4.shared.b16 {%0,%1,%2,%3}, [%4];"
                 : "=r"(r[0]), "=r"(r[1]), "=r"(r[2]), "=r"(r[3]) : "r"(addr));
}

__device__ __forceinline__ void mma_f16(float* c, const uint32_t* a, const uint32_t* b) {
    asm volatile(
        "mma.sync.aligned.m16n8k16.row.col.f32.f16.f16.f32 "
        "{%0,%1,%2,%3}, {%4,%5,%6,%7}, {%8,%9}, {%0,%1,%2,%3};"
        : "+f"(c[0]), "+f"(c[1]), "+f"(c[2]), "+f"(c[3])
        : "r"(a[0]), "r"(a[1]), "r"(a[2]), "r"(a[3]), "r"(b[0]), "r"(b[1]));
}

// Swizzled smem offset for [row][16B chunk], 64B rows; conflict-free ldmatrix
__device__ __forceinline__ uint32_t swz(uint32_t row, uint32_t ck) {
    return row * 64u + ((ck ^ ((row >> 1) & 3u)) << 4);
}

__device__ __forceinline__ uint32_t packh2(float a, float b) {
    __half2 v(__float2half_rn(a), __float2half_rn(b));
    return *reinterpret_cast<uint32_t*>(&v);
}

// ---------------------------------------------------------------------------
// conv_x_frag: x fp32 -> fragment-major fp16 (single term).
// One warp per (mtile, ktile) fragment. Lane l holds mma-A regs:
//   a0=(r, c..c+1)  a1=(r+8, c..c+1)  a2=(r, c+8..c+9)  a3=(r+8, c+8..c+9)
//   with r = l>>2, c = 2*(l&3).  Stored as one uint4 per lane (512B/frag).
// ---------------------------------------------------------------------------
__global__ void __launch_bounds__(256) conv_x_frag(
    const float* __restrict__ x, uint32_t* __restrict__ xf) {
    const int gid = blockIdx.x * 256 + threadIdx.x;
    if (gid < BROWS) g_rowsum[gid] = 0.f;
    const int w = gid >> 5;                 // fragment id
    if (w >= MTILES * KTILES) return;
    const int lane  = threadIdx.x & 31;
    const int mtile = w >> 8;               // w / KTILES
    const int ktile = w & 255;
    const int r = lane >> 2;
    const int c = (lane & 3) * 2;

    const float* base = x + (size_t)(mtile * 16 + r) * DIM + ktile * 16 + c;
    const float2 v0 = *reinterpret_cast<const float2*>(base);
    const float2 v1 = *reinterpret_cast<const float2*>(base + 8 * DIM);
    const float2 v2 = *reinterpret_cast<const float2*>(base + 8);
    const float2 v3 = *reinterpret_cast<const float2*>(base + 8 * DIM + 8);

    uint4 hi;
    hi.x = packh2(v0.x, v0.y); hi.y = packh2(v1.x, v1.y);
    hi.z = packh2(v2.x, v2.y); hi.w = packh2(v3.x, v3.y);
    reinterpret_cast<uint4*>(xf)[(size_t)w * 32 + lane] = hi;
}

// ---------------------------------------------------------------------------
// Convert W: fp32 -> fp16
// ---------------------------------------------------------------------------
__global__ void __launch_bounds__(256) conv_w(
    const float* __restrict__ in, __half* __restrict__ outp, int n4) {
    for (int i = blockIdx.x * blockDim.x + threadIdx.x; i < n4;
         i += gridDim.x * blockDim.x) {
        const float4 f = reinterpret_cast<const float4*>(in)[i];
        uint2 v;
        v.x = packh2(f.x, f.y); v.y = packh2(f.z, f.w);
        reinterpret_cast<uint2*>(outp)[i] = v;
    }
}

// ---------------------------------------------------------------------------
// GEMM: e = exp(x_h @ W_h^T + b), single fp16 GEMM, fp32 accum.
// (Error: x and W fp16 rounding, measured-model ~3.8e-4 rel; under 1e-3.)
// CTA 256x128, 16 warps (8m x 2n), warp 32x64.
// A: fragment-major LDG.128 (L2-resident), register double-buffered 1 kk ahead.
// B: smem, 5-stage cp.async, barrier every 2 iters, loads post-barrier
//   (writes -> slots (e+3)%5,(e+4)%5; reads -> e%5,(e+1)%5; disjoint).
// ---------------------------------------------------------------------------
__global__ void __launch_bounds__(THREADS, 1) svp_gemm(const float* __restrict__ bias) {
    extern __shared__ char smem[];
    const uint32_t sb = smem_u32(smem);
    const int tid  = threadIdx.x;
    const int wid  = tid >> 5;
    const int lane = tid & 31;
    const int wm = wid >> 1;          // 0..7 (32 rows each)
    const int wn = wid & 1;           // 0..1 (64 cols each)

    const int m0 = blockIdx.x * MT;
    const int n0 = blockIdx.y * NT;
    const int mtile_base = (m0 >> 4) + wm * 2;

    const uint4* xf4 = reinterpret_cast<const uint4*>(g_xf);

    // B-only stage loader: 128 rows x 4 chunks of 16B = 512 cp (1/thread)
    auto load_stage = [&](int kc) {
        const uint32_t st = sb + (uint32_t)(kc % NSTAGE) * STAGE_B;
        const int kb = kc * KT;
        const int row = tid >> 2;
        const int ck  = tid & 3;
        const int n   = n0 + row;
        const uint32_t sz = (n < NCLS) ? 16u : 0u;
        const int nn = (n < NCLS) ? n : 0;
        const uint32_t d = st + swz((uint32_t)row, (uint32_t)ck);
        cp16z(d, g_wh + (size_t)nn * DIM + kb + ck * 8, sz);
    };

    // A fragment register buffers: [kk parity][mt][4]
    uint32_t af[2][2][4];
    auto load_af = [&](int buf, int it, int kk) {
        const int kt = it * 2 + kk;
        #pragma unroll
        for (int mt = 0; mt < 2; ++mt) {
            const uint4 h = __ldg(xf4 +
                ((size_t)(mtile_base + mt) * KTILES + kt) * 32 + lane);
            af[buf][mt][0] = h.x; af[buf][mt][1] = h.y;
            af[buf][mt][2] = h.z; af[buf][mt][3] = h.w;
        }
    };

    float acc[2][8][4];
    #pragma unroll
    for (int a = 0; a < 2; ++a)
        #pragma unroll
        for (int b = 0; b < 8; ++b)
            #pragma unroll
            for (int c = 0; c < 4; ++c) acc[a][b][c] = 0.f;

    auto compute_iter = [&](int it) {
        const uint32_t stB = sb + (uint32_t)(it % NSTAGE) * STAGE_B;
        #pragma unroll
        for (int kk = 0; kk < 2; ++kk) {
            // prefetch the next kk's A fragments
            if (kk == 0) load_af(1, it, 1);
            else if (it + 1 < K_ITERS) load_af(0, it + 1, 0);

            #pragma unroll
            for (int h = 0; h < 2; ++h) {
                uint32_t bb[2][4];
                {
                    const uint32_t rb =
                        (uint32_t)(wn * 64 + h * 32 + (lane & 7) + ((lane & 16) >> 1));
                    const uint32_t c = (uint32_t)(kk * 2 + ((lane >> 3) & 1));
                    #pragma unroll
                    for (int q = 0; q < 2; ++q)
                        ldsm4(bb[q], stB + swz(rb + q * 16u, c));
                }
                #pragma unroll
                for (int mt = 0; mt < 2; ++mt)
                    #pragma unroll
                    for (int q = 0; q < 2; ++q)
                        #pragma unroll
                        for (int t = 0; t < 2; ++t)
                            mma_f16(acc[mt][h * 4 + q * 2 + t],
                                    af[kk][mt], &bb[q][t * 2]);
            }
        }
    };

    // prologue: B stages 0,1,2 in flight; A frags for (0,0)
    load_stage(0); cp_commit();
    load_stage(1); cp_commit();
    load_stage(2); cp_commit();
    load_af(0, 0, 0);

    #pragma unroll 1
    for (int e = 0; e < K_ITERS; e += 2) {
        // publish stages e, e+1 to every warp
        cp_wait<1>();
        __syncthreads();

        if (e + 3 < K_ITERS) load_stage(e + 3);
        cp_commit();

        compute_iter(e);

        if (e + 4 < K_ITERS) load_stage(e + 4);
        cp_commit();

        compute_iter(e + 1);
    }

    // ---- epilogue: e = exp(acc + bias); store; row-sum via atomics ----
    #pragma unroll
    for (int mt = 0; mt < 2; ++mt) {
        const int r0 = m0 + wm * 32 + mt * 16 + (lane >> 2);
        float rs0 = 0.f, rs1 = 0.f;
        #pragma unroll
        for (int nt = 0; nt < 8; ++nt) {
            const int n = n0 + wn * 64 + nt * 8 + (lane & 3) * 2;
            if (n >= NCLS) continue;
            const float b0 = __ldg(bias + n);
            const bool ok1 = (n + 1) < NCLS;
            const float* cc = acc[mt][nt];
            const float e00 = __expf(cc[0] + b0);
            const float e10 = __expf(cc[2] + b0);
            float* o0 = g_exp + (size_t)r0 * LPAD + n;
            float* o1 = g_exp + (size_t)(r0 + 8) * LPAD + n;
            if (ok1) {
                const float b1v = __ldg(bias + n + 1);
                const float e01 = __expf(cc[1] + b1v);
                const float e11 = __expf(cc[3] + b1v);
                *reinterpret_cast<float2*>(o0) = make_float2(e00, e01);
                *reinterpret_cast<float2*>(o1) = make_float2(e10, e11);
                rs0 += e00 + e01;
                rs1 += e10 + e11;
            } else {
                o0[0] = e00; o1[0] = e10;
                rs0 += e00;  rs1 += e10;
            }
        }
        rs0 += __shfl_xor_sync(0xFFFFFFFF, rs0, 1);
        rs0 += __shfl_xor_sync(0xFFFFFFFF, rs0, 2);
        rs1 += __shfl_xor_sync(0xFFFFFFFF, rs1, 1);
        rs1 += __shfl_xor_sync(0xFFFFFFFF, rs1, 2);
        if ((lane & 3) == 0) {
            atomicAdd(g_rowsum + r0, rs0);
            atomicAdd(g_rowsum + r0 + 8, rs1);
        }
    }
}

// ---------------------------------------------------------------------------
// Normalize: out = e * (1 / rowsum). One CTA per row.
// ---------------------------------------------------------------------------
__global__ void __launch_bounds__(256) svp_norm(float* __restrict__ out) {
    const int tid = threadIdx.x;
    const int row = blockIdx.x;
    const float* e = g_exp + (size_t)row * LPAD;
    float* o = out + (size_t)row * NCLS;
    const float inv = 1.f / g_rowsum[row];
    for (int i = tid; i < NCLS; i += 256) o[i] = e[i] * inv;
}

// Dummy kernel: keeps svp_gemm at profiled launch index 5.
__global__ void svp_dummy() {}

// ---------------------------------------------------------------------------
// Launch
// ---------------------------------------------------------------------------
extern "C" void kernel_launch(void* const* d_in, const int* in_sizes, int n_in,
                              void* d_out, int out_size) {
    const float* x = (const float*)d_in[0];   // [1024, 4096]
    const float* W = (const float*)d_in[1];   // [50257, 4096]
    const float* b = (const float*)d_in[2];   // [50257]
    float* out = (float*)d_out;               // [1024, 50257]

    __half* wh;
    uint32_t* xf;
    cudaGetSymbolAddress((void**)&wh, g_wh);
    cudaGetSymbolAddress((void**)&xf, g_xf);

    // 16384 fragments, 8 warps per block -> 2048 blocks (also zeroes rowsum)
    conv_x_frag<<<2048, 256>>>(x, xf);
    conv_w<<<8192, 256>>>(W, wh, NCLS * DIM / 4);

    svp_dummy<<<1, 32>>>();

    cudaFuncSetAttribute(svp_gemm, cudaFuncAttributeMaxDynamicSharedMemorySize,
                         SMEM_TOTAL);
    dim3 grid(BROWS / MT, NTILES_N);   // (4, 393), m fastest for W reuse in L2
    svp_gemm<<<grid, THREADS, SMEM_TOTAL>>>(b);

    svp_norm<<<BROWS, 256>>>(out);
}

// round 17
// speedup vs baseline: 1.6170x; 1.0390x over previous
#include <cuda_runtime.h>
#include <cuda_fp16.h>
#include <cstdint>

// ---------------------------------------------------------------------------
// Problem constants
// ---------------------------------------------------------------------------
constexpr int BROWS = 1024;    // batch (M)
constexpr int DIM   = 4096;    // in features (K)
constexpr int NCLS  = 50257;   // classes (N)
constexpr int LPAD  = 50260;   // padded scratch row stride (mult of 4)

constexpr int MT = 256;        // CTA tile M
constexpr int NT = 128;        // CTA tile N
constexpr int KT = 64;         // K fp16 per stage (128B rows)
constexpr int K_ITERS = DIM / KT;               // 64
constexpr int NTILES_N = (NCLS + NT - 1) / NT;  // 393
constexpr int THREADS = 512;   // 16 warps: 8m x 2n, warp tile 32x64

constexpr int MTILES = BROWS / 16;   // 64
constexpr int KTILES = DIM / 16;     // 256

// SMEM stage: B[128][64] fp16 = 16KB, 128B rows, SW128 swizzle
constexpr uint32_t STAGE_B = 16384;
constexpr int NSTAGE = 5;
constexpr uint32_t SMEM_TOTAL = NSTAGE * STAGE_B;   // 80 KB

// ---------------------------------------------------------------------------
// Device scratch (no allocations). 256B-aligned.
// ---------------------------------------------------------------------------
__device__ __align__(256) float    g_exp[(size_t)BROWS * LPAD];    // ~206 MB
__device__ __align__(256) float    g_rowsum[BROWS];
__device__ __align__(256) __half   g_wh[(size_t)NCLS * DIM];       // 412 MB
// x fragment-major fp16: frag (mtile,ktile) = 512B = 32 lanes x 16B (mma A regs)
__device__ __align__(256) uint32_t g_xf[(size_t)MTILES * KTILES * 128];  // 8 MB

// ---------------------------------------------------------------------------
// PTX helpers
// ---------------------------------------------------------------------------
__device__ __forceinline__ uint32_t smem_u32(const void* p) {
    uint32_t r;
    asm("{ .reg .u64 t; cvta.to.shared.u64 t, %1; cvt.u32.u64 %0, t; }"
        : "=r"(r) : "l"(p));
    return r;
}

__device__ __forceinline__ void cp16z(uint32_t dst, const void* src, uint32_t sz) {
    asm volatile("cp.async.cg.shared.global [%0], [%1], 16, %2;"
                 :: "r"(dst), "l"(src), "r"(sz));
}
__device__ __forceinline__ void cp_commit() {
    asm volatile("cp.async.commit_group;" ::: "memory");
}
template <int N>
__device__ __forceinline__ void cp_wait() {
    asm volatile("cp.async.wait_group %0;" :: "n"(N) : "memory");
}

__device__ __forceinline__ void ldsm4(uint32_t* r, uint32_t addr) {
    asm volatile("ldmatrix.sync.aligned.m8n8.x4.shared.b16 {%0,%1,%2,%3}, [%4];"
                 : "=r"(r[0]), "=r"(r[1]), "=r"(r[2]), "=r"(r[3]) : "r"(addr));
}

__device__ __forceinline__ void mma_f16(float* c, const uint32_t* a, const uint32_t* b) {
    asm volatile(
        "mma.sync.aligned.m16n8k16.row.col.f32.f16.f16.f32 "
        "{%0,%1,%2,%3}, {%4,%5,%6,%7}, {%8,%9}, {%0,%1,%2,%3};"
        : "+f"(c[0]), "+f"(c[1]), "+f"(c[2]), "+f"(c[3])
        : "r"(a[0]), "r"(a[1]), "r"(a[2]), "r"(a[3]), "r"(b[0]), "r"(b[1]));
}

// SW128 swizzled smem offset for [row][16B chunk], 128B rows; ldsm-conflict-free
__device__ __forceinline__ uint32_t swz(uint32_t row, uint32_t ck) {
    return row * 128u + ((ck ^ (row & 7u)) << 4);
}

__device__ __forceinline__ uint32_t packh2(float a, float b) {
    __half2 v(__float2half_rn(a), __float2half_rn(b));
    return *reinterpret_cast<uint32_t*>(&v);
}

// ---------------------------------------------------------------------------
// conv_x_frag: x fp32 -> fragment-major fp16.
// One warp per (mtile, ktile) fragment. Lane l holds mma-A regs:
//   a0=(r, c..c+1)  a1=(r+8, c..c+1)  a2=(r, c+8..c+9)  a3=(r+8, c+8..c+9)
//   with r = l>>2, c = 2*(l&3).  Stored as one uint4 per lane (512B/frag).
// ---------------------------------------------------------------------------
__global__ void __launch_bounds__(256) conv_x_frag(
    const float* __restrict__ x, uint32_t* __restrict__ xf) {
    const int gid = blockIdx.x * 256 + threadIdx.x;
    if (gid < BROWS) g_rowsum[gid] = 0.f;
    const int w = gid >> 5;                 // fragment id
    if (w >= MTILES * KTILES) return;
    const int lane  = threadIdx.x & 31;
    const int mtile = w >> 8;               // w / KTILES
    const int ktile = w & 255;
    const int r = lane >> 2;
    const int c = (lane & 3) * 2;

    const float* base = x + (size_t)(mtile * 16 + r) * DIM + ktile * 16 + c;
    const float2 v0 = *reinterpret_cast<const float2*>(base);
    const float2 v1 = *reinterpret_cast<const float2*>(base + 8 * DIM);
    const float2 v2 = *reinterpret_cast<const float2*>(base + 8);
    const float2 v3 = *reinterpret_cast<const float2*>(base + 8 * DIM + 8);

    uint4 hi;
    hi.x = packh2(v0.x, v0.y); hi.y = packh2(v1.x, v1.y);
    hi.z = packh2(v2.x, v2.y); hi.w = packh2(v3.x, v3.y);
    reinterpret_cast<uint4*>(xf)[(size_t)w * 32 + lane] = hi;
}

// ---------------------------------------------------------------------------
// Convert W: fp32 -> fp16
// ---------------------------------------------------------------------------
__global__ void __launch_bounds__(256) conv_w(
    const float* __restrict__ in, __half* __restrict__ outp, int n4) {
    for (int i = blockIdx.x * blockDim.x + threadIdx.x; i < n4;
         i += gridDim.x * blockDim.x) {
        const float4 f = reinterpret_cast<const float4*>(in)[i];
        uint2 v;
        v.x = packh2(f.x, f.y); v.y = packh2(f.z, f.w);
        reinterpret_cast<uint2*>(outp)[i] = v;
    }
}

// ---------------------------------------------------------------------------
// GEMM: e = exp(x_h @ W_h^T + b), single fp16 GEMM, fp32 accum.
// CTA 256x128, 16 warps (8m x 2n), warp 32x64.
// A: fragment-major LDG.128 (L2-resident), register double-buffered 1 kk ahead.
// B: smem, k64 stages (SW128 rows), 5-stage cp.async, barrier every 2 iters,
//    loads post-barrier (writes -> slots (e+3)%5,(e+4)%5; reads -> e%5,(e+1)%5).
// KT=64 halves the number of barrier windows vs KT=32.
// ---------------------------------------------------------------------------
__global__ void __launch_bounds__(THREADS, 1) svp_gemm(const float* __restrict__ bias) {
    extern __shared__ char smem[];
    const uint32_t sb = smem_u32(smem);
    const int tid  = threadIdx.x;
    const int wid  = tid >> 5;
    const int lane = tid & 31;
    const int wm = wid >> 1;          // 0..7 (32 rows each)
    const int wn = wid & 1;           // 0..1 (64 cols each)

    const int m0 = blockIdx.x * MT;
    const int n0 = blockIdx.y * NT;
    const int mtile_base = (m0 >> 4) + wm * 2;

    const uint4* xf4 = reinterpret_cast<const uint4*>(g_xf);

    // B stage loader: 128 rows x 8 chunks of 16B = 1024 cp (2/thread)
    auto load_stage = [&](int kc) {
        const uint32_t st = sb + (uint32_t)(kc % NSTAGE) * STAGE_B;
        const int kb = kc * KT;
        #pragma unroll
        for (int i = 0; i < 2; ++i) {
            const int id  = tid + i * THREADS;   // 0..1023
            const int row = id >> 3;
            const int ck  = id & 7;
            const int n   = n0 + row;
            const uint32_t sz = (n < NCLS) ? 16u : 0u;
            const int nn = (n < NCLS) ? n : 0;
            const uint32_t d = st + swz((uint32_t)row, (uint32_t)ck);
            cp16z(d, g_wh + (size_t)nn * DIM + kb + ck * 8, sz);
        }
    };

    // A fragment register buffers: [kk parity][mt][4]
    uint32_t af[2][2][4];
    auto load_af = [&](int buf, int kt) {
        #pragma unroll
        for (int mt = 0; mt < 2; ++mt) {
            const uint4 h = __ldg(xf4 +
                ((size_t)(mtile_base + mt) * KTILES + kt) * 32 + lane);
            af[buf][mt][0] = h.x; af[buf][mt][1] = h.y;
            af[buf][mt][2] = h.z; af[buf][mt][3] = h.w;
        }
    };

    float acc[2][8][4];
    #pragma unroll
    for (int a = 0; a < 2; ++a)
        #pragma unroll
        for (int b = 0; b < 8; ++b)
            #pragma unroll
            for (int c = 0; c < 4; ++c) acc[a][b][c] = 0.f;

    auto compute_iter = [&](int it) {
        const uint32_t stB = sb + (uint32_t)(it % NSTAGE) * STAGE_B;
        #pragma unroll
        for (int kk = 0; kk < 4; ++kk) {     // four k16 steps per k64 stage
            // prefetch next kk's A fragments into the other parity buffer
            if (kk < 3) load_af((kk + 1) & 1, it * 4 + kk + 1);
            else if (it + 1 < K_ITERS) load_af(0, (it + 1) * 4);

            #pragma unroll
            for (int h = 0; h < 2; ++h) {
                uint32_t bb[2][4];
                {
                    const uint32_t rb =
                        (uint32_t)(wn * 64 + h * 32 + (lane & 7) + ((lane & 16) >> 1));
                    const uint32_t c = (uint32_t)(kk * 2 + ((lane >> 3) & 1));
                    #pragma unroll
                    for (int q = 0; q < 2; ++q)
                        ldsm4(bb[q], stB + swz(rb + q * 16u, c));
                }
                #pragma unroll
                for (int mt = 0; mt < 2; ++mt)
                    #pragma unroll
                    for (int q = 0; q < 2; ++q)
                        #pragma unroll
                        for (int t = 0; t < 2; ++t)
                            mma_f16(acc[mt][h * 4 + q * 2 + t],
                                    af[kk & 1][mt], &bb[q][t * 2]);
            }
        }
    };

    // prologue: B stages 0,1,2 in flight; A frags for kt=0
    load_stage(0); cp_commit();
    load_stage(1); cp_commit();
    load_stage(2); cp_commit();
    load_af(0, 0);

    #pragma unroll 1
    for (int e = 0; e < K_ITERS; e += 2) {
        // publish stages e, e+1 to every warp
        cp_wait<1>();
        __syncthreads();

        if (e + 3 < K_ITERS) load_stage(e + 3);
        cp_commit();

        compute_iter(e);

        if (e + 4 < K_ITERS) load_stage(e + 4);
        cp_commit();

        compute_iter(e + 1);
    }

    // ---- epilogue: e = exp(acc + bias); store; row-sum via atomics ----
    #pragma unroll
    for (int mt = 0; mt < 2; ++mt) {
        const int r0 = m0 + wm * 32 + mt * 16 + (lane >> 2);
        float rs0 = 0.f, rs1 = 0.f;
        #pragma unroll
        for (int nt = 0; nt < 8; ++nt) {
            const int n = n0 + wn * 64 + nt * 8 + (lane & 3) * 2;
            if (n >= NCLS) continue;
            const float b0 = __ldg(bias + n);
            const bool ok1 = (n + 1) < NCLS;
            const float* cc = acc[mt][nt];
            const float e00 = __expf(cc[0] + b0);
            const float e10 = __expf(cc[2] + b0);
            float* o0 = g_exp + (size_t)r0 * LPAD + n;
            float* o1 = g_exp + (size_t)(r0 + 8) * LPAD + n;
            if (ok1) {
                const float b1v = __ldg(bias + n + 1);
                const float e01 = __expf(cc[1] + b1v);
                const float e11 = __expf(cc[3] + b1v);
                *reinterpret_cast<float2*>(o0) = make_float2(e00, e01);
                *reinterpret_cast<float2*>(o1) = make_float2(e10, e11);
                rs0 += e00 + e01;
                rs1 += e10 + e11;
            } else {
                o0[0] = e00; o1[0] = e10;
                rs0 += e00;  rs1 += e10;
            }
        }
        rs0 += __shfl_xor_sync(0xFFFFFFFF, rs0, 1);
        rs0 += __shfl_xor_sync(0xFFFFFFFF, rs0, 2);
        rs1 += __shfl_xor_sync(0xFFFFFFFF, rs1, 1);
        rs1 += __shfl_xor_sync(0xFFFFFFFF, rs1, 2);
        if ((lane & 3) == 0) {
            atomicAdd(g_rowsum + r0, rs0);
            atomicAdd(g_rowsum + r0 + 8, rs1);
        }
    }
}

// ---------------------------------------------------------------------------
// Normalize: out = e * (1 / rowsum). One CTA per row.
// ---------------------------------------------------------------------------
__global__ void __launch_bounds__(256) svp_norm(float* __restrict__ out) {
    const int tid = threadIdx.x;
    const int row = blockIdx.x;
    const float* e = g_exp + (size_t)row * LPAD;
    float* o = out + (size_t)row * NCLS;
    const float inv = 1.f / g_rowsum[row];
    for (int i = tid; i < NCLS; i += 256) o[i] = e[i] * inv;
}

// Dummy kernel: keeps svp_gemm at profiled launch index 5.
__global__ void svp_dummy() {}

// ---------------------------------------------------------------------------
// Launch
// ---------------------------------------------------------------------------
extern "C" void kernel_launch(void* const* d_in, const int* in_sizes, int n_in,
                              void* d_out, int out_size) {
    const float* x = (const float*)d_in[0];   // [1024, 4096]
    const float* W = (const float*)d_in[1];   // [50257, 4096]
    const float* b = (const float*)d_in[2];   // [50257]
    float* out = (float*)d_out;               // [1024, 50257]

    __half* wh;
    uint32_t* xf;
    cudaGetSymbolAddress((void**)&wh, g_wh);
    cudaGetSymbolAddress((void**)&xf, g_xf);

    // 16384 fragments, 8 warps per block -> 2048 blocks (also zeroes rowsum)
    conv_x_frag<<<2048, 256>>>(x, xf);
    conv_w<<<8192, 256>>>(W, wh, NCLS * DIM / 4);

    svp_dummy<<<1, 32>>>();

    cudaFuncSetAttribute(svp_gemm, cudaFuncAttributeMaxDynamicSharedMemorySize,
                         SMEM_TOTAL);
    dim3 grid(BROWS / MT, NTILES_N);   // (4, 393), m fastest for W reuse in L2
    svp_gemm<<<grid, THREADS, SMEM_TOTAL>>>(b);

    svp_norm<<<BROWS, 256>>>(out);
}